// round 5
// baseline (speedup 1.0000x reference)
#include <cuda_runtime.h>
#include <math.h>

#define FRAMES 2048
#define BEPS 1e-5f

typedef unsigned long long ull;

// ---------------- scratch ----------------
__device__ __align__(16) float g_y1[FRAMES * 16 * 144];   // [2048,16,12,12]
__device__ float g_c[FRAMES];
__device__ int   g_p[32];
__device__ int   g_chain[6][32];
__device__ int   g_chain_len[6];

__device__ __forceinline__ float fast_tanh(float x) {
    return 1.0f - 2.0f / (1.0f + __expf(2.0f * x));
}
__device__ __forceinline__ float tanhap(float x) {
    float y;
    asm("tanh.approx.f32 %0, %1;" : "=f"(y) : "f"(x));
    return y;
}
__device__ __forceinline__ float sigap(float x) {
    return fmaf(0.5f, tanhap(0.5f * x), 0.5f);
}
__device__ __forceinline__ ull fma2(ull a, ull b, ull c) {
    ull d;
    asm("fma.rn.f32x2 %0, %1, %2, %3;" : "=l"(d) : "l"(a), "l"(b), "l"(c));
    return d;
}
__device__ __forceinline__ ull add2(ull a, ull b) {
    ull d;
    asm("add.rn.f32x2 %0, %1, %2;" : "=l"(d) : "l"(a), "l"(b));
    return d;
}
__device__ __forceinline__ ull pack2(float lo, float hi) {
    ull d;
    asm("mov.b64 %0, {%1, %2};" : "=l"(d) : "f"(lo), "f"(hi));
    return d;
}
__device__ __forceinline__ float lo2(ull a) { return __uint_as_float((unsigned)(a & 0xffffffffu)); }
__device__ __forceinline__ float hi2(ull a) { return __uint_as_float((unsigned)(a >> 32)); }
__device__ __forceinline__ float acc4(float acc, float4 a, float4 b) {
    acc = fmaf(a.x, b.x, acc);
    acc = fmaf(a.y, b.y, acc);
    acc = fmaf(a.z, b.z, acc);
    acc = fmaf(a.w, b.w, acc);
    return acc;
}

// ---------------- Kernel A: conv1 + bias + BN + ReLU + 3x3/3 maxpool ----------
// grid (2048,12), 96 threads: thread = (px 0..11, chp 0..7) -> 2 channels each.
// f32x2 accumulation over K; 48 ull weights register-resident.
__global__ void __launch_bounds__(96) conv1_kernel(
    const float* __restrict__ x,
    const float* __restrict__ w,        // [16,3,4,4]
    const float* __restrict__ bias,
    const float* __restrict__ bg, const float* __restrict__ bb,
    const float* __restrict__ bm, const float* __restrict__ bv)
{
    __shared__ float4 smem[1296];       // 3 * 12 * 36 float4
    const int f  = blockIdx.x;
    const int py = blockIdx.y;
    const int tid = threadIdx.x;

    const float4* xin = (const float4*)x;
    const long base = (long)f * 15552 + (long)py * 432;
    for (int i = tid; i < 1296; i += 96) {
        int ic  = i / 432;
        int rem = i - ic * 432;
        smem[i] = xin[base + (long)ic * 5184 + rem];
    }
    __syncthreads();

    const int chp = tid & 7;
    const int px  = tid >> 3;
    const int ch0 = 2 * chp, ch1 = ch0 + 1;

    ull wp0[24], wp1[24];
    {
        const ull* w0 = (const ull*)(w + ch0 * 48);
        const ull* w1 = (const ull*)(w + ch1 * 48);
        #pragma unroll
        for (int j = 0; j < 24; j++) { wp0[j] = w0[j]; wp1[j] = w1[j]; }
    }
    const float s0 = bg[ch0] * rsqrtf(bv[ch0] + BEPS);
    const float s1 = bg[ch1] * rsqrtf(bv[ch1] + BEPS);
    const float t0 = bb[ch0] - bm[ch0] * s0;
    const float t1 = bb[ch1] - bm[ch1] * s1;
    const float cb0 = bias[ch0], cb1 = bias[ch1];

    float m0 = -1e30f, m1 = -1e30f;
    #pragma unroll
    for (int sy = 0; sy < 3; sy++) {
        #pragma unroll
        for (int sx = 0; sx < 3; sx++) {
            ull A0 = 0, B0 = 0, A1 = 0, B1 = 0;
            #pragma unroll
            for (int ic = 0; ic < 3; ic++) {
                #pragma unroll
                for (int ky = 0; ky < 4; ky++) {
                    const ulonglong2 v = *(const ulonglong2*)
                        &smem[(ic * 12 + sy * 4 + ky) * 36 + px * 3 + sx];
                    const int wi = (ic * 4 + ky) * 2;
                    A0 = fma2(v.x, wp0[wi], A0);
                    B0 = fma2(v.y, wp0[wi + 1], B0);
                    A1 = fma2(v.x, wp1[wi], A1);
                    B1 = fma2(v.y, wp1[wi + 1], B1);
                }
            }
            const ull S0 = add2(A0, B0);
            const ull S1 = add2(A1, B1);
            const float a0 = lo2(S0) + hi2(S0) + cb0;
            const float a1 = lo2(S1) + hi2(S1) + cb1;
            m0 = fmaxf(m0, fmaxf(fmaf(a0, s0, t0), 0.0f));
            m1 = fmaxf(m1, fmaxf(fmaf(a1, s1, t1), 0.0f));
        }
    }
    g_y1[((f * 16 + ch0) * 12 + py) * 12 + px] = m0;
    g_y1[((f * 16 + ch1) * 12 + py) * 12 + px] = m1;
}

// ---------------- Kernel B: conv2 -> scalar per frame ------------------------
__global__ void __launch_bounds__(256) conv2_kernel(
    const float* __restrict__ w2, const float* __restrict__ b2p,
    const float* __restrict__ bg, const float* __restrict__ bb,
    const float* __restrict__ bm, const float* __restrict__ bv)
{
    const int f = blockIdx.x * 8 + (threadIdx.x >> 5);
    const int lane = threadIdx.x & 31;
    const int ch = lane & 15, half = lane >> 4;

    const float4* wf4 = (const float4*)w2;
    const float4 wa = wf4[ch * 4 + half * 2 + 0];
    const float4 wb = wf4[ch * 4 + half * 2 + 1];

    const float scale = bg[0] * rsqrtf(bv[0] + BEPS);
    const float shift = bb[0] - bm[0] * scale;
    const float cb = b2p[0];

    const float4* y4 = (const float4*)g_y1;
    const long cbase = ((long)f * 16 + ch) * 36;

    float best = -1e30f;
    #pragma unroll
    for (int sy = 0; sy < 3; sy++) {
        #pragma unroll
        for (int sx = 0; sx < 3; sx++) {
            int ky0 = half * 2;
            float4 va = y4[cbase + (sy * 4 + ky0) * 3 + sx];
            float4 vb = y4[cbase + (sy * 4 + ky0 + 1) * 3 + sx];
            float acc = acc4(acc4(0.0f, va, wa), vb, wb);
            #pragma unroll
            for (int off = 16; off; off >>= 1)
                acc += __shfl_xor_sync(0xffffffffu, acc, off);
            float val = fmaxf(fmaf(acc + cb, scale, shift), 0.0f);
            best = fmaxf(best, val);
        }
    }
    if (lane == 0) g_c[f] = best;
}

// ---------------- Kernel C: gating MLP + argmax + chain build ----------------
__global__ void __launch_bounds__(1024) gate_kernel(
    const float* __restrict__ w1, const float* __restrict__ b1,
    const float* __restrict__ w2, const float* __restrict__ b2,
    const float* __restrict__ w3, const float* __restrict__ b3)
{
    __shared__ float sc[32][65];
    __shared__ float sh1[32][33];
    __shared__ float sh2[32][33];
    __shared__ float sw1[2048];
    __shared__ float sw2[1024];
    const int tid = threadIdx.x;
    const int s = tid >> 5, j = tid & 31;

    for (int i = tid; i < 2048; i += 1024) {
        sc[i >> 6][i & 63] = g_c[i];
        sw1[i] = w1[i];
    }
    if (tid < 1024) sw2[tid] = w2[tid];
    __syncthreads();

    {
        float acc = b1[j];
        #pragma unroll 8
        for (int t = 0; t < 64; t++) acc = fmaf(sc[s][t], sw1[j * 64 + t], acc);
        sh1[s][j] = fast_tanh(acc);
    }
    __syncthreads();
    {
        float acc = b2[j];
        #pragma unroll
        for (int t = 0; t < 32; t++) acc = fmaf(sh1[s][t], sw2[j * 32 + t], acc);
        sh2[s][j] = fast_tanh(acc);
    }
    __syncthreads();

    if (tid < 32) {
        float bestv = -1e30f; int besti = 0;
        #pragma unroll
        for (int a = 0; a < 6; a++) {
            float acc = b3[a];
            #pragma unroll
            for (int t = 0; t < 32; t++) acc = fmaf(sh2[tid][t], w3[a * 32 + t], acc);
            if (acc > bestv) { bestv = acc; besti = a; }
        }
        g_p[tid] = besti;
    }
    __syncthreads();

    if (tid == 0) {
        int cnt[6] = {0, 0, 0, 0, 0, 0};
        for (int b = 0; b < 32; b++) {
            int e = g_p[b];
            g_chain[e][cnt[e]++] = b;
        }
        for (int e = 0; e < 6; e++) g_chain_len[e] = cnt[e];
    }
}

// ---------------- Kernel D: single-warp per-expert LSTM, zero barriers -------
// 6 blocks x 32 threads. Lane k owns h[k], c[k]. h broadcast via shfl only.
// f32x2 packs gate PAIRS: Wif[j] = (Whh_i[k][j], Whh_f[k][j]); Wgo likewise.
__global__ void __launch_bounds__(32) lstm_kernel(
    const float* __restrict__ wih,   // [6,128,1]
    const float* __restrict__ whh,   // [6,128,32]
    const float* __restrict__ bih,   // [6,128]
    const float* __restrict__ bhh,   // [6,128]
    const float* __restrict__ hn0,   // [6,32]
    const float* __restrict__ outw,  // [6,64]
    const float* __restrict__ outb,  // [6]
    float* __restrict__ out)         // [32,6]
{
    const int e = blockIdx.x;
    const int k = threadIdx.x;
    const int len = g_chain_len[e];
    if (len == 0) return;

    ull Wif[32], Wgo[32];
    {
        const float* wb = whh + (long)e * 4096;
        #pragma unroll
        for (int j = 0; j < 32; j++) {
            Wif[j] = pack2(wb[(0  + k) * 32 + j], wb[(32 + k) * 32 + j]);
            Wgo[j] = pack2(wb[(64 + k) * 32 + j], wb[(96 + k) * 32 + j]);
        }
    }
    const ull wxif = pack2(wih[e * 128 + 0  + k], wih[e * 128 + 32 + k]);
    const ull wxgo = pack2(wih[e * 128 + 64 + k], wih[e * 128 + 96 + k]);
    const ull bif  = pack2(bih[e * 128 + 0  + k] + bhh[e * 128 + 0  + k],
                           bih[e * 128 + 32 + k] + bhh[e * 128 + 32 + k]);
    const ull bgo  = pack2(bih[e * 128 + 64 + k] + bhh[e * 128 + 64 + k],
                           bih[e * 128 + 96 + k] + bhh[e * 128 + 96 + k]);

    float h = hn0[e * 32 + k];

    __shared__ float scx[64];
    __shared__ float sr[64];

    for (int s = 0; s < len; s++) {
        const int b = g_chain[e][s];
        scx[k]      = g_c[b * 64 + k];
        scx[k + 32] = g_c[b * 64 + 32 + k];
        float cst = 0.0f;
        __syncwarp();

        #pragma unroll 2
        for (int t = 0; t < 64; t++) {
            const float xt = scx[t];
            const ull xtd = pack2(xt, xt);
            ull aif0 = fma2(wxif, xtd, bif), ago0 = fma2(wxgo, xtd, bgo);
            ull aif1 = 0, aif2 = 0, aif3 = 0;
            ull ago1 = 0, ago2 = 0, ago3 = 0;
            #pragma unroll
            for (int m = 0; m < 8; m++) {
                const float h0 = __shfl_sync(0xffffffffu, h, 4 * m + 0);
                const float h1 = __shfl_sync(0xffffffffu, h, 4 * m + 1);
                const float h2 = __shfl_sync(0xffffffffu, h, 4 * m + 2);
                const float h3 = __shfl_sync(0xffffffffu, h, 4 * m + 3);
                const ull hd0 = pack2(h0, h0);
                const ull hd1 = pack2(h1, h1);
                const ull hd2 = pack2(h2, h2);
                const ull hd3 = pack2(h3, h3);
                aif0 = fma2(Wif[4 * m + 0], hd0, aif0);
                ago0 = fma2(Wgo[4 * m + 0], hd0, ago0);
                aif1 = fma2(Wif[4 * m + 1], hd1, aif1);
                ago1 = fma2(Wgo[4 * m + 1], hd1, ago1);
                aif2 = fma2(Wif[4 * m + 2], hd2, aif2);
                ago2 = fma2(Wgo[4 * m + 2], hd2, ago2);
                aif3 = fma2(Wif[4 * m + 3], hd3, aif3);
                ago3 = fma2(Wgo[4 * m + 3], hd3, ago3);
            }
            const ull aif = add2(add2(aif0, aif1), add2(aif2, aif3));
            const ull ago = add2(add2(ago0, ago1), add2(ago2, ago3));
            const float ai = lo2(aif), af = hi2(aif);
            const float ag = lo2(ago), ao = hi2(ago);

            const float ig = sigap(ai);
            const float fg = sigap(af);
            const float gg = tanhap(ag);
            const float og = sigap(ao);
            cst = fmaf(fg, cst, ig * gg);
            h = og * tanhap(cst);
            if (k == 31) sr[t] = h;
        }

        __syncwarp();
        if (k < 6) {
            float acc = outb[k];
            #pragma unroll 8
            for (int t = 0; t < 64; t++) acc = fmaf(sr[t], outw[k * 64 + t], acc);
            out[b * 6 + k] = acc;
        }
        __syncwarp();
    }
}

// ---------------- launch ----------------
extern "C" void kernel_launch(void* const* d_in, const int* in_sizes, int n_in,
                              void* d_out, int out_size)
{
    const float* x       = (const float*)d_in[0];
    const float* conv1_w = (const float*)d_in[1];
    const float* conv1_b = (const float*)d_in[2];
    const float* bn1_g   = (const float*)d_in[3];
    const float* bn1_b   = (const float*)d_in[4];
    const float* bn1_m   = (const float*)d_in[5];
    const float* bn1_v   = (const float*)d_in[6];
    const float* conv2_w = (const float*)d_in[7];
    const float* conv2_b = (const float*)d_in[8];
    const float* bn2_g   = (const float*)d_in[9];
    const float* bn2_b   = (const float*)d_in[10];
    const float* bn2_m   = (const float*)d_in[11];
    const float* bn2_v   = (const float*)d_in[12];
    const float* pre_w1  = (const float*)d_in[13];
    const float* pre_b1  = (const float*)d_in[14];
    const float* pre_w2  = (const float*)d_in[15];
    const float* pre_b2  = (const float*)d_in[16];
    const float* pre_w3  = (const float*)d_in[17];
    const float* pre_b3  = (const float*)d_in[18];
    const float* lstm_wih = (const float*)d_in[19];
    const float* lstm_whh = (const float*)d_in[20];
    const float* lstm_bih = (const float*)d_in[21];
    const float* lstm_bhh = (const float*)d_in[22];
    const float* hn0     = (const float*)d_in[23];
    const float* out_w   = (const float*)d_in[24];
    const float* out_b   = (const float*)d_in[25];
    float* out = (float*)d_out;

    dim3 gridA(FRAMES, 12);
    conv1_kernel<<<gridA, 96>>>(x, conv1_w, conv1_b, bn1_g, bn1_b, bn1_m, bn1_v);
    conv2_kernel<<<FRAMES / 8, 256>>>(conv2_w, conv2_b, bn2_g, bn2_b, bn2_m, bn2_v);
    gate_kernel<<<1, 1024>>>(pre_w1, pre_b1, pre_w2, pre_b2, pre_w3, pre_b3);
    lstm_kernel<<<6, 32>>>(lstm_wih, lstm_whh, lstm_bih, lstm_bhh, hn0, out_w, out_b, out);
}

// round 7
// speedup vs baseline: 1.6813x; 1.6813x over previous
#include <cuda_runtime.h>
#include <math.h>

#define FRAMES 2048
#define BEPS 1e-5f

typedef unsigned long long ull;

// ---------------- scratch ----------------
__device__ __align__(16) float g_y1[FRAMES * 16 * 144];   // [2048,16,12,12]
__device__ float g_c[FRAMES];
__device__ int   g_p[32];
__device__ int   g_chain[6][32];
__device__ int   g_chain_len[6];

__device__ __forceinline__ float fast_tanh(float x) {
    return 1.0f - 2.0f / (1.0f + __expf(2.0f * x));
}
__device__ __forceinline__ float tanhap(float x) {
    float y;
    asm("tanh.approx.f32 %0, %1;" : "=f"(y) : "f"(x));
    return y;
}
__device__ __forceinline__ float sigap(float x) {
    return fmaf(0.5f, tanhap(0.5f * x), 0.5f);
}
__device__ __forceinline__ ull fma2(ull a, ull b, ull c) {
    ull d;
    asm("fma.rn.f32x2 %0, %1, %2, %3;" : "=l"(d) : "l"(a), "l"(b), "l"(c));
    return d;
}
__device__ __forceinline__ ull add2(ull a, ull b) {
    ull d;
    asm("add.rn.f32x2 %0, %1, %2;" : "=l"(d) : "l"(a), "l"(b));
    return d;
}
__device__ __forceinline__ float lo2(ull a) { return __uint_as_float((unsigned)(a & 0xffffffffu)); }
__device__ __forceinline__ float hi2(ull a) { return __uint_as_float((unsigned)(a >> 32)); }
__device__ __forceinline__ float acc4(float acc, float4 a, float4 b) {
    acc = fmaf(a.x, b.x, acc);
    acc = fmaf(a.y, b.y, acc);
    acc = fmaf(a.z, b.z, acc);
    acc = fmaf(a.w, b.w, acc);
    return acc;
}

// ---------------- Kernel A: conv1 + bias + BN + ReLU + 3x3/3 maxpool ----------
// grid (2048,12), 192 threads: thread = (px 0..11, ch 0..15), one channel each.
// FRONT-BATCHED staging: 6 independent LDG.128 per thread (+tail), then STS.
// f32x2 accumulation over the K dimension.
__global__ void __launch_bounds__(192) conv1_kernel(
    const float* __restrict__ x,
    const float* __restrict__ w,        // [16,3,4,4]
    const float* __restrict__ bias,
    const float* __restrict__ bg, const float* __restrict__ bb,
    const float* __restrict__ bm, const float* __restrict__ bv)
{
    __shared__ float4 smem[1296];       // 3 * 12 * 36 float4
    const int f  = blockIdx.x;
    const int py = blockIdx.y;
    const int tid = threadIdx.x;
    const int ch = tid & 15;
    const int px = tid >> 4;            // 0..11

    const float4* xin = (const float4*)x;
    const long base = (long)f * 15552 + (long)py * 432;

    // ---- batched global loads (independent -> high MLP) ----
    float4 r[6];
    #pragma unroll
    for (int j = 0; j < 6; j++) {
        const int i = tid + j * 192;
        const int ic = i / 432;
        r[j] = xin[base + i + ic * 4752];        // ic*5184 + (i - ic*432)
    }
    const bool extra = tid < 144;
    float4 r6;
    if (extra) r6 = xin[base + (tid + 1152) + 2 * 4752];   // ic==2 for i>=1152

    // weights for this channel: 24 packed pairs (independent loads, overlap)
    ull wp[24];
    {
        const ull* wsrc = (const ull*)(w + ch * 48);
        #pragma unroll
        for (int j = 0; j < 24; j++) wp[j] = wsrc[j];
    }
    const float scale = bg[ch] * rsqrtf(bv[ch] + BEPS);
    const float shift = bb[ch] - bm[ch] * scale;
    const float cb = bias[ch];

    // ---- stores to smem ----
    #pragma unroll
    for (int j = 0; j < 6; j++) smem[tid + j * 192] = r[j];
    if (extra) smem[tid + 1152] = r6;
    __syncthreads();

    float m = -1e30f;
    #pragma unroll
    for (int sy = 0; sy < 3; sy++) {
        #pragma unroll
        for (int sx = 0; sx < 3; sx++) {
            ull A = 0, B = 0;
            #pragma unroll
            for (int ic = 0; ic < 3; ic++) {
                #pragma unroll
                for (int ky = 0; ky < 4; ky++) {
                    const ulonglong2 v = *(const ulonglong2*)
                        &smem[(ic * 12 + sy * 4 + ky) * 36 + px * 3 + sx];
                    const int wi = (ic * 4 + ky) * 2;
                    A = fma2(v.x, wp[wi], A);
                    B = fma2(v.y, wp[wi + 1], B);
                }
            }
            const ull S = add2(A, B);
            const float a = lo2(S) + hi2(S) + cb;
            m = fmaxf(m, fmaxf(fmaf(a, scale, shift), 0.0f));
        }
    }
    g_y1[((f * 16 + ch) * 12 + py) * 12 + px] = m;
}

// ---------------- Kernel B: conv2 -> scalar per frame ------------------------
__global__ void __launch_bounds__(256) conv2_kernel(
    const float* __restrict__ w2, const float* __restrict__ b2p,
    const float* __restrict__ bg, const float* __restrict__ bb,
    const float* __restrict__ bm, const float* __restrict__ bv)
{
    const int f = blockIdx.x * 8 + (threadIdx.x >> 5);
    const int lane = threadIdx.x & 31;
    const int ch = lane & 15, half = lane >> 4;

    const float4* wf4 = (const float4*)w2;
    const float4 wa = wf4[ch * 4 + half * 2 + 0];
    const float4 wb = wf4[ch * 4 + half * 2 + 1];

    const float scale = bg[0] * rsqrtf(bv[0] + BEPS);
    const float shift = bb[0] - bm[0] * scale;
    const float cb = b2p[0];

    const float4* y4 = (const float4*)g_y1;
    const long cbase = ((long)f * 16 + ch) * 36;

    float best = -1e30f;
    #pragma unroll
    for (int sy = 0; sy < 3; sy++) {
        #pragma unroll
        for (int sx = 0; sx < 3; sx++) {
            int ky0 = half * 2;
            float4 va = y4[cbase + (sy * 4 + ky0) * 3 + sx];
            float4 vb = y4[cbase + (sy * 4 + ky0 + 1) * 3 + sx];
            float acc = acc4(acc4(0.0f, va, wa), vb, wb);
            #pragma unroll
            for (int off = 16; off; off >>= 1)
                acc += __shfl_xor_sync(0xffffffffu, acc, off);
            float val = fmaxf(fmaf(acc + cb, scale, shift), 0.0f);
            best = fmaxf(best, val);
        }
    }
    if (lane == 0) g_c[f] = best;
}

// ---------------- Kernel C: gating MLP + argmax + chain build ----------------
__global__ void __launch_bounds__(1024) gate_kernel(
    const float* __restrict__ w1, const float* __restrict__ b1,
    const float* __restrict__ w2, const float* __restrict__ b2,
    const float* __restrict__ w3, const float* __restrict__ b3)
{
    __shared__ float sc[32][65];
    __shared__ float sh1[32][33];
    __shared__ float sh2[32][33];
    __shared__ float sw1[2048];
    __shared__ float sw2[1024];
    const int tid = threadIdx.x;
    const int s = tid >> 5, j = tid & 31;

    for (int i = tid; i < 2048; i += 1024) {
        sc[i >> 6][i & 63] = g_c[i];
        sw1[i] = w1[i];
    }
    if (tid < 1024) sw2[tid] = w2[tid];
    __syncthreads();

    {
        float acc = b1[j];
        #pragma unroll 8
        for (int t = 0; t < 64; t++) acc = fmaf(sc[s][t], sw1[j * 64 + t], acc);
        sh1[s][j] = fast_tanh(acc);
    }
    __syncthreads();
    {
        float acc = b2[j];
        #pragma unroll
        for (int t = 0; t < 32; t++) acc = fmaf(sh1[s][t], sw2[j * 32 + t], acc);
        sh2[s][j] = fast_tanh(acc);
    }
    __syncthreads();

    if (tid < 32) {
        float bestv = -1e30f; int besti = 0;
        #pragma unroll
        for (int a = 0; a < 6; a++) {
            float acc = b3[a];
            #pragma unroll
            for (int t = 0; t < 32; t++) acc = fmaf(sh2[tid][t], w3[a * 32 + t], acc);
            if (acc > bestv) { bestv = acc; besti = a; }
        }
        g_p[tid] = besti;
    }
    __syncthreads();

    if (tid == 0) {
        int cnt[6] = {0, 0, 0, 0, 0, 0};
        for (int b = 0; b < 32; b++) {
            int e = g_p[b];
            g_chain[e][cnt[e]++] = b;
        }
        for (int e = 0; e < 6; e++) g_chain_len[e] = cnt[e];
    }
}

// ---------------- Kernel D: 4-warp per-expert LSTM + output head (R3) --------
__global__ void __launch_bounds__(128) lstm_kernel(
    const float* __restrict__ wih,
    const float* __restrict__ whh,
    const float* __restrict__ bih,
    const float* __restrict__ bhh,
    const float* __restrict__ hn0,
    const float* __restrict__ outw,
    const float* __restrict__ outb,
    float* __restrict__ out)
{
    const int e = blockIdx.x;
    const int tid = threadIdx.x;
    const int w = tid >> 5;
    const int k = tid & 31;
    const int len = g_chain_len[e];
    if (len == 0) return;

    const int row = 32 * w + k;
    float W[32];
    {
        const float4* wr = (const float4*)(whh + (long)e * 4096 + (long)row * 32);
        #pragma unroll
        for (int j = 0; j < 8; j++) {
            float4 v = wr[j];
            W[4 * j + 0] = v.x; W[4 * j + 1] = v.y;
            W[4 * j + 2] = v.z; W[4 * j + 3] = v.w;
        }
    }
    const float wx   = wih[e * 128 + row];
    const float bsum = bih[e * 128 + row] + bhh[e * 128 + row];
    const bool  isg  = (w == 2);

    float h = hn0[e * 32 + k];

    __shared__ float4 actb[2][32];
    __shared__ float  scx[64];
    __shared__ float  sr[64];

    for (int s = 0; s < len; s++) {
        const int b = g_chain[e][s];
        if (w == 0) {
            scx[k]      = g_c[b * 64 + k];
            scx[k + 32] = g_c[b * 64 + 32 + k];
        }
        float cst = 0.0f;
        __syncthreads();

        #pragma unroll 2
        for (int t = 0; t < 64; t++) {
            const float xt = scx[t];
            float a = fmaf(wx, xt, bsum);
            float a0 = 0.0f, a1 = 0.0f, a2 = 0.0f, a3 = 0.0f;
            #pragma unroll
            for (int m = 0; m < 8; m++) {
                float h0 = __shfl_sync(0xffffffffu, h, 4 * m + 0);
                float h1 = __shfl_sync(0xffffffffu, h, 4 * m + 1);
                float h2 = __shfl_sync(0xffffffffu, h, 4 * m + 2);
                float h3 = __shfl_sync(0xffffffffu, h, 4 * m + 3);
                a0 = fmaf(W[4 * m + 0], h0, a0);
                a1 = fmaf(W[4 * m + 1], h1, a1);
                a2 = fmaf(W[4 * m + 2], h2, a2);
                a3 = fmaf(W[4 * m + 3], h3, a3);
            }
            a += (a0 + a1) + (a2 + a3);
            const float act = isg ? tanhap(a) : sigap(a);
            ((float*)(&actb[t & 1][k]))[w] = act;
            __syncthreads();

            const float4 g4 = actb[t & 1][k];
            cst = fmaf(g4.y, cst, g4.x * g4.z);
            h = g4.w * tanhap(cst);
            if (w == 0 && k == 31) sr[t] = h;
        }

        if (w == 0) {
            __syncwarp();
            if (k < 6) {
                float acc = outb[k];
                #pragma unroll 8
                for (int t = 0; t < 64; t++) acc = fmaf(sr[t], outw[k * 64 + t], acc);
                out[b * 6 + k] = acc;
            }
        }
    }
}

// ---------------- launch ----------------
extern "C" void kernel_launch(void* const* d_in, const int* in_sizes, int n_in,
                              void* d_out, int out_size)
{
    const float* x       = (const float*)d_in[0];
    const float* conv1_w = (const float*)d_in[1];
    const float* conv1_b = (const float*)d_in[2];
    const float* bn1_g   = (const float*)d_in[3];
    const float* bn1_b   = (const float*)d_in[4];
    const float* bn1_m   = (const float*)d_in[5];
    const float* bn1_v   = (const float*)d_in[6];
    const float* conv2_w = (const float*)d_in[7];
    const float* conv2_b = (const float*)d_in[8];
    const float* bn2_g   = (const float*)d_in[9];
    const float* bn2_b   = (const float*)d_in[10];
    const float* bn2_m   = (const float*)d_in[11];
    const float* bn2_v   = (const float*)d_in[12];
    const float* pre_w1  = (const float*)d_in[13];
    const float* pre_b1  = (const float*)d_in[14];
    const float* pre_w2  = (const float*)d_in[15];
    const float* pre_b2  = (const float*)d_in[16];
    const float* pre_w3  = (const float*)d_in[17];
    const float* pre_b3  = (const float*)d_in[18];
    const float* lstm_wih = (const float*)d_in[19];
    const float* lstm_whh = (const float*)d_in[20];
    const float* lstm_bih = (const float*)d_in[21];
    const float* lstm_bhh = (const float*)d_in[22];
    const float* hn0     = (const float*)d_in[23];
    const float* out_w   = (const float*)d_in[24];
    const float* out_b   = (const float*)d_in[25];
    float* out = (float*)d_out;

    dim3 gridA(FRAMES, 12);
    conv1_kernel<<<gridA, 192>>>(x, conv1_w, conv1_b, bn1_g, bn1_b, bn1_m, bn1_v);
    conv2_kernel<<<FRAMES / 8, 256>>>(conv2_w, conv2_b, bn2_g, bn2_b, bn2_m, bn2_v);
    gate_kernel<<<1, 1024>>>(pre_w1, pre_b1, pre_w2, pre_b2, pre_w3, pre_b3);
    lstm_kernel<<<6, 128>>>(lstm_wih, lstm_whh, lstm_bih, lstm_bhh, hn0, out_w, out_b, out);
}

// round 10
// speedup vs baseline: 1.8332x; 1.0904x over previous
#include <cuda_runtime.h>
#include <math.h>

#define FRAMES 2048
#define BEPS 1e-5f

typedef unsigned long long ull;

// ---------------- scratch ----------------
__device__ __align__(16) float g_y1[FRAMES * 16 * 144];   // [2048,16,12,12]
__device__ float g_c[FRAMES];
__device__ int   g_p[32];
__device__ int   g_chain[6][32];
__device__ int   g_chain_len[6];

__device__ __forceinline__ float fast_tanh(float x) {
    return 1.0f - 2.0f / (1.0f + __expf(2.0f * x));
}
__device__ __forceinline__ float tanhap(float x) {
    float y;
    asm("tanh.approx.f32 %0, %1;" : "=f"(y) : "f"(x));
    return y;
}
__device__ __forceinline__ float sigap(float x) {
    return fmaf(0.5f, tanhap(0.5f * x), 0.5f);
}
__device__ __forceinline__ ull fma2(ull a, ull b, ull c) {
    ull d;
    asm("fma.rn.f32x2 %0, %1, %2, %3;" : "=l"(d) : "l"(a), "l"(b), "l"(c));
    return d;
}
__device__ __forceinline__ ull add2(ull a, ull b) {
    ull d;
    asm("add.rn.f32x2 %0, %1, %2;" : "=l"(d) : "l"(a), "l"(b));
    return d;
}
__device__ __forceinline__ float lo2(ull a) { return __uint_as_float((unsigned)(a & 0xffffffffu)); }
__device__ __forceinline__ float hi2(ull a) { return __uint_as_float((unsigned)(a >> 32)); }
__device__ __forceinline__ float acc4(float acc, float4 a, float4 b) {
    acc = fmaf(a.x, b.x, acc);
    acc = fmaf(a.y, b.y, acc);
    acc = fmaf(a.z, b.z, acc);
    acc = fmaf(a.w, b.w, acc);
    return acc;
}

// ---------------- Kernel A: conv1 + bias + BN + ReLU + 3x3/3 maxpool ----------
// grid (2048,12), 96 threads: thread = (px 0..11, chp 0..7) -> 2 channels.
// Staging via cp.async (no staging registers -> weights can live in regs).
// f32x2 accumulation over K; LDS traffic halved vs 1ch/thread.
__global__ void __launch_bounds__(96) conv1_kernel(
    const float* __restrict__ x,
    const float* __restrict__ w,        // [16,3,4,4]
    const float* __restrict__ bias,
    const float* __restrict__ bg, const float* __restrict__ bb,
    const float* __restrict__ bm, const float* __restrict__ bv)
{
    __shared__ float4 smem[1296];       // 3 * 12 * 36 float4 = 20736 B
    const int f  = blockIdx.x;
    const int py = blockIdx.y;
    const int tid = threadIdx.x;

    const float4* xin = (const float4*)x;
    const long base = (long)f * 15552 + (long)py * 432;   // f4 units
    const unsigned sbase = (unsigned)__cvta_generic_to_shared(smem);

    // ---- async staging: 13 per thread + tail (tid<48), no registers used ----
    #pragma unroll
    for (int j = 0; j < 13; j++) {
        const int i = tid + j * 96;
        const int ic = i / 432;
        asm volatile("cp.async.cg.shared.global [%0], [%1], 16;\n"
                     :: "r"(sbase + i * 16), "l"(xin + base + i + ic * 4752));
    }
    if (tid < 48) {
        const int i = tid + 1248;       // ic == 2
        asm volatile("cp.async.cg.shared.global [%0], [%1], 16;\n"
                     :: "r"(sbase + i * 16), "l"(xin + base + i + 2 * 4752));
    }
    asm volatile("cp.async.commit_group;\n");

    // ---- overlap: load weights/BN params while cp.async fills smem ----
    const int chp = tid & 7;
    const int px  = tid >> 3;
    const int ch0 = 2 * chp, ch1 = ch0 + 1;

    ull wp0[24], wp1[24];
    {
        const ull* w0 = (const ull*)(w + ch0 * 48);
        const ull* w1 = (const ull*)(w + ch1 * 48);
        #pragma unroll
        for (int j = 0; j < 24; j++) { wp0[j] = w0[j]; wp1[j] = w1[j]; }
    }
    const float s0 = bg[ch0] * rsqrtf(bv[ch0] + BEPS);
    const float s1 = bg[ch1] * rsqrtf(bv[ch1] + BEPS);
    const float t0 = bb[ch0] - bm[ch0] * s0;
    const float t1 = bb[ch1] - bm[ch1] * s1;
    const float cb0 = bias[ch0], cb1 = bias[ch1];

    asm volatile("cp.async.wait_group 0;\n");
    __syncthreads();

    float m0 = -1e30f, m1 = -1e30f;
    #pragma unroll
    for (int sy = 0; sy < 3; sy++) {
        #pragma unroll
        for (int sx = 0; sx < 3; sx++) {
            ull A0 = 0, B0 = 0, A1 = 0, B1 = 0;
            #pragma unroll
            for (int ic = 0; ic < 3; ic++) {
                #pragma unroll
                for (int ky = 0; ky < 4; ky++) {
                    const ulonglong2 v = *(const ulonglong2*)
                        &smem[(ic * 12 + sy * 4 + ky) * 36 + px * 3 + sx];
                    const int wi = (ic * 4 + ky) * 2;
                    A0 = fma2(v.x, wp0[wi], A0);
                    B0 = fma2(v.y, wp0[wi + 1], B0);
                    A1 = fma2(v.x, wp1[wi], A1);
                    B1 = fma2(v.y, wp1[wi + 1], B1);
                }
            }
            const ull S0 = add2(A0, B0);
            const ull S1 = add2(A1, B1);
            const float a0 = lo2(S0) + hi2(S0) + cb0;
            const float a1 = lo2(S1) + hi2(S1) + cb1;
            m0 = fmaxf(m0, fmaxf(fmaf(a0, s0, t0), 0.0f));
            m1 = fmaxf(m1, fmaxf(fmaf(a1, s1, t1), 0.0f));
        }
    }
    g_y1[((f * 16 + ch0) * 12 + py) * 12 + px] = m0;
    g_y1[((f * 16 + ch1) * 12 + py) * 12 + px] = m1;
}

// ---------------- Kernel B: conv2 -> scalar per frame ------------------------
__global__ void __launch_bounds__(256) conv2_kernel(
    const float* __restrict__ w2, const float* __restrict__ b2p,
    const float* __restrict__ bg, const float* __restrict__ bb,
    const float* __restrict__ bm, const float* __restrict__ bv)
{
    const int f = blockIdx.x * 8 + (threadIdx.x >> 5);
    const int lane = threadIdx.x & 31;
    const int ch = lane & 15, half = lane >> 4;

    const float4* wf4 = (const float4*)w2;
    const float4 wa = wf4[ch * 4 + half * 2 + 0];
    const float4 wb = wf4[ch * 4 + half * 2 + 1];

    const float scale = bg[0] * rsqrtf(bv[0] + BEPS);
    const float shift = bb[0] - bm[0] * scale;
    const float cb = b2p[0];

    const float4* y4 = (const float4*)g_y1;
    const long cbase = ((long)f * 16 + ch) * 36;

    float best = -1e30f;
    #pragma unroll
    for (int sy = 0; sy < 3; sy++) {
        #pragma unroll
        for (int sx = 0; sx < 3; sx++) {
            int ky0 = half * 2;
            float4 va = y4[cbase + (sy * 4 + ky0) * 3 + sx];
            float4 vb = y4[cbase + (sy * 4 + ky0 + 1) * 3 + sx];
            float acc = acc4(acc4(0.0f, va, wa), vb, wb);
            #pragma unroll
            for (int off = 16; off; off >>= 1)
                acc += __shfl_xor_sync(0xffffffffu, acc, off);
            float val = fmaxf(fmaf(acc + cb, scale, shift), 0.0f);
            best = fmaxf(best, val);
        }
    }
    if (lane == 0) g_c[f] = best;
}

// ---------------- Kernel C: gating MLP + argmax + chain build ----------------
__global__ void __launch_bounds__(1024) gate_kernel(
    const float* __restrict__ w1, const float* __restrict__ b1,
    const float* __restrict__ w2, const float* __restrict__ b2,
    const float* __restrict__ w3, const float* __restrict__ b3)
{
    __shared__ float sc[32][65];
    __shared__ float sh1[32][33];
    __shared__ float sh2[32][33];
    __shared__ float sw1[2048];
    __shared__ float sw2[1024];
    const int tid = threadIdx.x;
    const int s = tid >> 5, j = tid & 31;

    for (int i = tid; i < 2048; i += 1024) {
        sc[i >> 6][i & 63] = g_c[i];
        sw1[i] = w1[i];
    }
    if (tid < 1024) sw2[tid] = w2[tid];
    __syncthreads();

    {
        float acc = b1[j];
        #pragma unroll 8
        for (int t = 0; t < 64; t++) acc = fmaf(sc[s][t], sw1[j * 64 + t], acc);
        sh1[s][j] = fast_tanh(acc);
    }
    __syncthreads();
    {
        float acc = b2[j];
        #pragma unroll
        for (int t = 0; t < 32; t++) acc = fmaf(sh1[s][t], sw2[j * 32 + t], acc);
        sh2[s][j] = fast_tanh(acc);
    }
    __syncthreads();

    if (tid < 32) {
        float bestv = -1e30f; int besti = 0;
        #pragma unroll
        for (int a = 0; a < 6; a++) {
            float acc = b3[a];
            #pragma unroll
            for (int t = 0; t < 32; t++) acc = fmaf(sh2[tid][t], w3[a * 32 + t], acc);
            if (acc > bestv) { bestv = acc; besti = a; }
        }
        g_p[tid] = besti;
    }
    __syncthreads();

    if (tid == 0) {
        int cnt[6] = {0, 0, 0, 0, 0, 0};
        for (int b = 0; b < 32; b++) {
            int e = g_p[b];
            g_chain[e][cnt[e]++] = b;
        }
        for (int e = 0; e < 6; e++) g_chain_len[e] = cnt[e];
    }
}

// ---------------- Kernel D: 4-warp per-expert LSTM + output head -------------
__global__ void __launch_bounds__(128) lstm_kernel(
    const float* __restrict__ wih,
    const float* __restrict__ whh,
    const float* __restrict__ bih,
    const float* __restrict__ bhh,
    const float* __restrict__ hn0,
    const float* __restrict__ outw,
    const float* __restrict__ outb,
    float* __restrict__ out)
{
    const int e = blockIdx.x;
    const int tid = threadIdx.x;
    const int w = tid >> 5;
    const int k = tid & 31;
    const int len = g_chain_len[e];
    if (len == 0) return;

    const int row = 32 * w + k;
    float W[32];
    {
        const float4* wr = (const float4*)(whh + (long)e * 4096 + (long)row * 32);
        #pragma unroll
        for (int j = 0; j < 8; j++) {
            float4 v = wr[j];
            W[4 * j + 0] = v.x; W[4 * j + 1] = v.y;
            W[4 * j + 2] = v.z; W[4 * j + 3] = v.w;
        }
    }
    const float wx   = wih[e * 128 + row];
    const float bsum = bih[e * 128 + row] + bhh[e * 128 + row];
    const bool  isg  = (w == 2);

    float h = hn0[e * 32 + k];

    __shared__ float4 actb[2][32];
    __shared__ float  scx[64];
    __shared__ float  sr[64];

    for (int s = 0; s < len; s++) {
        const int b = g_chain[e][s];
        if (w == 0) {
            scx[k]      = g_c[b * 64 + k];
            scx[k + 32] = g_c[b * 64 + 32 + k];
        }
        float cst = 0.0f;
        __syncthreads();

        #pragma unroll 2
        for (int t = 0; t < 64; t++) {
            const float xt = scx[t];
            float a = fmaf(wx, xt, bsum);
            float a0 = 0.0f, a1 = 0.0f, a2 = 0.0f, a3 = 0.0f;
            #pragma unroll
            for (int m = 0; m < 8; m++) {
                float h0 = __shfl_sync(0xffffffffu, h, 4 * m + 0);
                float h1 = __shfl_sync(0xffffffffu, h, 4 * m + 1);
                float h2 = __shfl_sync(0xffffffffu, h, 4 * m + 2);
                float h3 = __shfl_sync(0xffffffffu, h, 4 * m + 3);
                a0 = fmaf(W[4 * m + 0], h0, a0);
                a1 = fmaf(W[4 * m + 1], h1, a1);
                a2 = fmaf(W[4 * m + 2], h2, a2);
                a3 = fmaf(W[4 * m + 3], h3, a3);
            }
            a += (a0 + a1) + (a2 + a3);
            const float act = isg ? tanhap(a) : sigap(a);
            ((float*)(&actb[t & 1][k]))[w] = act;
            __syncthreads();

            const float4 g4 = actb[t & 1][k];
            cst = fmaf(g4.y, cst, g4.x * g4.z);
            h = g4.w * tanhap(cst);
            if (w == 0 && k == 31) sr[t] = h;
        }

        if (w == 0) {
            __syncwarp();
            if (k < 6) {
                float acc = outb[k];
                #pragma unroll 8
                for (int t = 0; t < 64; t++) acc = fmaf(sr[t], outw[k * 64 + t], acc);
                out[b * 6 + k] = acc;
            }
        }
    }
}

// ---------------- launch ----------------
extern "C" void kernel_launch(void* const* d_in, const int* in_sizes, int n_in,
                              void* d_out, int out_size)
{
    const float* x       = (const float*)d_in[0];
    const float* conv1_w = (const float*)d_in[1];
    const float* conv1_b = (const float*)d_in[2];
    const float* bn1_g   = (const float*)d_in[3];
    const float* bn1_b   = (const float*)d_in[4];
    const float* bn1_m   = (const float*)d_in[5];
    const float* bn1_v   = (const float*)d_in[6];
    const float* conv2_w = (const float*)d_in[7];
    const float* conv2_b = (const float*)d_in[8];
    const float* bn2_g   = (const float*)d_in[9];
    const float* bn2_b   = (const float*)d_in[10];
    const float* bn2_m   = (const float*)d_in[11];
    const float* bn2_v   = (const float*)d_in[12];
    const float* pre_w1  = (const float*)d_in[13];
    const float* pre_b1  = (const float*)d_in[14];
    const float* pre_w2  = (const float*)d_in[15];
    const float* pre_b2  = (const float*)d_in[16];
    const float* pre_w3  = (const float*)d_in[17];
    const float* pre_b3  = (const float*)d_in[18];
    const float* lstm_wih = (const float*)d_in[19];
    const float* lstm_whh = (const float*)d_in[20];
    const float* lstm_bih = (const float*)d_in[21];
    const float* lstm_bhh = (const float*)d_in[22];
    const float* hn0     = (const float*)d_in[23];
    const float* out_w   = (const float*)d_in[24];
    const float* out_b   = (const float*)d_in[25];
    float* out = (float*)d_out;

    dim3 gridA(FRAMES, 12);
    conv1_kernel<<<gridA, 96>>>(x, conv1_w, conv1_b, bn1_g, bn1_b, bn1_m, bn1_v);
    conv2_kernel<<<FRAMES / 8, 256>>>(conv2_w, conv2_b, bn2_g, bn2_b, bn2_m, bn2_v);
    gate_kernel<<<1, 1024>>>(pre_w1, pre_b1, pre_w2, pre_b2, pre_w3, pre_b3);
    lstm_kernel<<<6, 128>>>(lstm_wih, lstm_whh, lstm_bih, lstm_bhh, hn0, out_w, out_b, out);
}

// round 12
// speedup vs baseline: 2.0161x; 1.0998x over previous
#include <cuda_runtime.h>
#include <math.h>

#define FRAMES 2048
#define BEPS 1e-5f

typedef unsigned long long ull;

// ---------------- scratch ----------------
__device__ __align__(16) float g_y1[FRAMES * 16 * 144];   // [2048,16,12,12]
__device__ float g_c[FRAMES];
__device__ int   g_p[32];
__device__ int   g_chain[6][32];
__device__ int   g_chain_len[6];

__device__ __forceinline__ float fast_tanh(float x) {
    return 1.0f - 2.0f / (1.0f + __expf(2.0f * x));
}
__device__ __forceinline__ float tanhap(float x) {
    float y;
    asm("tanh.approx.f32 %0, %1;" : "=f"(y) : "f"(x));
    return y;
}
__device__ __forceinline__ float sigap(float x) {
    return fmaf(0.5f, tanhap(0.5f * x), 0.5f);
}
__device__ __forceinline__ ull fma2(ull a, ull b, ull c) {
    ull d;
    asm("fma.rn.f32x2 %0, %1, %2, %3;" : "=l"(d) : "l"(a), "l"(b), "l"(c));
    return d;
}
__device__ __forceinline__ ull add2(ull a, ull b) {
    ull d;
    asm("add.rn.f32x2 %0, %1, %2;" : "=l"(d) : "l"(a), "l"(b));
    return d;
}
__device__ __forceinline__ float lo2(ull a) { return __uint_as_float((unsigned)(a & 0xffffffffu)); }
__device__ __forceinline__ float hi2(ull a) { return __uint_as_float((unsigned)(a >> 32)); }
__device__ __forceinline__ float acc4(float acc, float4 a, float4 b) {
    acc = fmaf(a.x, b.x, acc);
    acc = fmaf(a.y, b.y, acc);
    acc = fmaf(a.z, b.z, acc);
    acc = fmaf(a.w, b.w, acc);
    return acc;
}

// ---------------- Kernel A: conv1 + bias + BN + ReLU + 3x3/3 maxpool ----------
// grid (2048,12), 128 threads. Compute phase: 108 threads = (px, sy, sx) sub-
// convs; x patch (48 floats) register-resident, 16 channels' weights streamed
// from SMEM as broadcasts. Zero x duplication through the crossbar.
// Pooling phase: 192 (px,ch) outputs with BN affine folded (applied pre-max).
__global__ void __launch_bounds__(128) conv1_kernel(
    const float* __restrict__ x,
    const float* __restrict__ w,        // [16,3,4,4]
    const float* __restrict__ bias,
    const float* __restrict__ bg, const float* __restrict__ bb,
    const float* __restrict__ bm, const float* __restrict__ bv)
{
    __shared__ float4 smem[1296];       // 3*12*36 float4 patch (20736 B)
    __shared__ float4 swt[192];         // 16ch * 12 float4 weights (3072 B)
    __shared__ float  sconv[9 * 12 * 16];  // sub-conv results (6912 B)

    const int f  = blockIdx.x;
    const int py = blockIdx.y;
    const int tid = threadIdx.x;

    const float4* xin = (const float4*)x;
    const long base = (long)f * 15552 + (long)py * 432;   // f4 units
    const unsigned sb_p = (unsigned)__cvta_generic_to_shared(smem);
    const unsigned sb_w = (unsigned)__cvta_generic_to_shared(swt);

    // ---- async staging: patch (1296 f4) + weights (192 f4) ----
    #pragma unroll
    for (int j = 0; j < 10; j++) {
        const int i = tid + j * 128;
        const int ic = i / 432;
        asm volatile("cp.async.cg.shared.global [%0], [%1], 16;\n"
                     :: "r"(sb_p + i * 16), "l"(xin + base + i + ic * 4752));
    }
    if (tid < 16) {
        const int i = 1280 + tid;       // ic == 2
        asm volatile("cp.async.cg.shared.global [%0], [%1], 16;\n"
                     :: "r"(sb_p + i * 16), "l"(xin + base + i + 2 * 4752));
    }
    {
        const float4* wg = (const float4*)w;
        asm volatile("cp.async.cg.shared.global [%0], [%1], 16;\n"
                     :: "r"(sb_w + tid * 16), "l"(wg + tid));
        if (tid < 64)
            asm volatile("cp.async.cg.shared.global [%0], [%1], 16;\n"
                         :: "r"(sb_w + (128 + tid) * 16), "l"(wg + 128 + tid));
    }
    asm volatile("cp.async.commit_group;\n");
    asm volatile("cp.async.wait_group 0;\n");
    __syncthreads();

    // ---- compute phase: one sub-conv (px, sy, sx), all 16 channels ----
    if (tid < 108) {
        const int px = tid % 12;
        const int s9 = tid / 12;        // sy*3+sx
        const int sy = s9 / 3, sx = s9 - sy * 3;

        ulonglong2 xr[12];
        #pragma unroll
        for (int ic = 0; ic < 3; ic++)
            #pragma unroll
            for (int ky = 0; ky < 4; ky++)
                xr[ic * 4 + ky] = *(const ulonglong2*)
                    &smem[(ic * 12 + sy * 4 + ky) * 36 + px * 3 + sx];

        #pragma unroll
        for (int ch = 0; ch < 16; ch++) {
            const ulonglong2* wch = (const ulonglong2*)(swt + ch * 12);
            ull A = 0, B = 0;
            #pragma unroll
            for (int r = 0; r < 12; r++) {
                const ulonglong2 wr = wch[r];     // broadcast (same addr)
                A = fma2(xr[r].x, wr.x, A);
                B = fma2(xr[r].y, wr.y, B);
            }
            const ull S = add2(A, B);
            sconv[(s9 * 12 + px) * 16 + ch] = lo2(S) + hi2(S);
        }
    }
    __syncthreads();

    // ---- pooling phase: 192 (px,ch) outputs; BN affine folded, pre-max ----
    {
        const int o = tid;              // 0..127
        const int px = o >> 4, ch = o & 15;
        const float scale = bg[ch] * rsqrtf(bv[ch] + BEPS);
        const float shift2 = bb[ch] - bm[ch] * scale + bias[ch] * scale;
        float m = -1e30f;
        #pragma unroll
        for (int s9 = 0; s9 < 9; s9++)
            m = fmaxf(m, fmaxf(fmaf(sconv[(s9 * 12 + px) * 16 + ch], scale, shift2), 0.0f));
        g_y1[((f * 16 + ch) * 12 + py) * 12 + px] = m;
    }
    if (tid < 64) {
        const int o = 128 + tid;
        const int px = o >> 4, ch = o & 15;
        const float scale = bg[ch] * rsqrtf(bv[ch] + BEPS);
        const float shift2 = bb[ch] - bm[ch] * scale + bias[ch] * scale;
        float m = -1e30f;
        #pragma unroll
        for (int s9 = 0; s9 < 9; s9++)
            m = fmaxf(m, fmaxf(fmaf(sconv[(s9 * 12 + px) * 16 + ch], scale, shift2), 0.0f));
        g_y1[((f * 16 + ch) * 12 + py) * 12 + px] = m;
    }
}

// ---------------- Kernel B: conv2 -> scalar per frame ------------------------
__global__ void __launch_bounds__(256) conv2_kernel(
    const float* __restrict__ w2, const float* __restrict__ b2p,
    const float* __restrict__ bg, const float* __restrict__ bb,
    const float* __restrict__ bm, const float* __restrict__ bv)
{
    const int f = blockIdx.x * 8 + (threadIdx.x >> 5);
    const int lane = threadIdx.x & 31;
    const int ch = lane & 15, half = lane >> 4;

    const float4* wf4 = (const float4*)w2;
    const float4 wa = wf4[ch * 4 + half * 2 + 0];
    const float4 wb = wf4[ch * 4 + half * 2 + 1];

    const float scale = bg[0] * rsqrtf(bv[0] + BEPS);
    const float shift = bb[0] - bm[0] * scale;
    const float cb = b2p[0];

    const float4* y4 = (const float4*)g_y1;
    const long cbase = ((long)f * 16 + ch) * 36;

    float best = -1e30f;
    #pragma unroll
    for (int sy = 0; sy < 3; sy++) {
        #pragma unroll
        for (int sx = 0; sx < 3; sx++) {
            int ky0 = half * 2;
            float4 va = y4[cbase + (sy * 4 + ky0) * 3 + sx];
            float4 vb = y4[cbase + (sy * 4 + ky0 + 1) * 3 + sx];
            float acc = acc4(acc4(0.0f, va, wa), vb, wb);
            #pragma unroll
            for (int off = 16; off; off >>= 1)
                acc += __shfl_xor_sync(0xffffffffu, acc, off);
            float val = fmaxf(fmaf(acc + cb, scale, shift), 0.0f);
            best = fmaxf(best, val);
        }
    }
    if (lane == 0) g_c[f] = best;
}

// ---------------- Kernel C: gating MLP + argmax + chain build ----------------
__global__ void __launch_bounds__(1024) gate_kernel(
    const float* __restrict__ w1, const float* __restrict__ b1,
    const float* __restrict__ w2, const float* __restrict__ b2,
    const float* __restrict__ w3, const float* __restrict__ b3)
{
    __shared__ float sc[32][65];
    __shared__ float sh1[32][33];
    __shared__ float sh2[32][33];
    __shared__ float sw1[2048];
    __shared__ float sw2[1024];
    const int tid = threadIdx.x;
    const int s = tid >> 5, j = tid & 31;

    for (int i = tid; i < 2048; i += 1024) {
        sc[i >> 6][i & 63] = g_c[i];
        sw1[i] = w1[i];
    }
    if (tid < 1024) sw2[tid] = w2[tid];
    __syncthreads();

    {
        float acc = b1[j];
        #pragma unroll 8
        for (int t = 0; t < 64; t++) acc = fmaf(sc[s][t], sw1[j * 64 + t], acc);
        sh1[s][j] = fast_tanh(acc);
    }
    __syncthreads();
    {
        float acc = b2[j];
        #pragma unroll
        for (int t = 0; t < 32; t++) acc = fmaf(sh1[s][t], sw2[j * 32 + t], acc);
        sh2[s][j] = fast_tanh(acc);
    }
    __syncthreads();

    if (tid < 32) {
        float bestv = -1e30f; int besti = 0;
        #pragma unroll
        for (int a = 0; a < 6; a++) {
            float acc = b3[a];
            #pragma unroll
            for (int t = 0; t < 32; t++) acc = fmaf(sh2[tid][t], w3[a * 32 + t], acc);
            if (acc > bestv) { bestv = acc; besti = a; }
        }
        g_p[tid] = besti;
    }
    __syncthreads();

    if (tid == 0) {
        int cnt[6] = {0, 0, 0, 0, 0, 0};
        for (int b = 0; b < 32; b++) {
            int e = g_p[b];
            g_chain[e][cnt[e]++] = b;
        }
        for (int e = 0; e < 6; e++) g_chain_len[e] = cnt[e];
    }
}

// ---------------- Kernel D: 4-warp per-expert LSTM + output head -------------
__global__ void __launch_bounds__(128) lstm_kernel(
    const float* __restrict__ wih,
    const float* __restrict__ whh,
    const float* __restrict__ bih,
    const float* __restrict__ bhh,
    const float* __restrict__ hn0,
    const float* __restrict__ outw,
    const float* __restrict__ outb,
    float* __restrict__ out)
{
    const int e = blockIdx.x;
    const int tid = threadIdx.x;
    const int w = tid >> 5;
    const int k = tid & 31;
    const int len = g_chain_len[e];
    if (len == 0) return;

    const int row = 32 * w + k;
    float W[32];
    {
        const float4* wr = (const float4*)(whh + (long)e * 4096 + (long)row * 32);
        #pragma unroll
        for (int j = 0; j < 8; j++) {
            float4 v = wr[j];
            W[4 * j + 0] = v.x; W[4 * j + 1] = v.y;
            W[4 * j + 2] = v.z; W[4 * j + 3] = v.w;
        }
    }
    const float wx   = wih[e * 128 + row];
    const float bsum = bih[e * 128 + row] + bhh[e * 128 + row];
    const bool  isg  = (w == 2);

    float h = hn0[e * 32 + k];

    __shared__ float4 actb[2][32];
    __shared__ float  scx[64];
    __shared__ float  sr[64];

    for (int s = 0; s < len; s++) {
        const int b = g_chain[e][s];
        if (w == 0) {
            scx[k]      = g_c[b * 64 + k];
            scx[k + 32] = g_c[b * 64 + 32 + k];
        }
        float cst = 0.0f;
        __syncthreads();

        #pragma unroll 2
        for (int t = 0; t < 64; t++) {
            const float xt = scx[t];
            float a = fmaf(wx, xt, bsum);
            float a0 = 0.0f, a1 = 0.0f, a2 = 0.0f, a3 = 0.0f;
            #pragma unroll
            for (int m = 0; m < 8; m++) {
                float h0 = __shfl_sync(0xffffffffu, h, 4 * m + 0);
                float h1 = __shfl_sync(0xffffffffu, h, 4 * m + 1);
                float h2 = __shfl_sync(0xffffffffu, h, 4 * m + 2);
                float h3 = __shfl_sync(0xffffffffu, h, 4 * m + 3);
                a0 = fmaf(W[4 * m + 0], h0, a0);
                a1 = fmaf(W[4 * m + 1], h1, a1);
                a2 = fmaf(W[4 * m + 2], h2, a2);
                a3 = fmaf(W[4 * m + 3], h3, a3);
            }
            a += (a0 + a1) + (a2 + a3);
            const float act = isg ? tanhap(a) : sigap(a);
            ((float*)(&actb[t & 1][k]))[w] = act;
            __syncthreads();

            const float4 g4 = actb[t & 1][k];
            cst = fmaf(g4.y, cst, g4.x * g4.z);
            h = g4.w * tanhap(cst);
            if (w == 0 && k == 31) sr[t] = h;
        }

        if (w == 0) {
            __syncwarp();
            if (k < 6) {
                float acc = outb[k];
                #pragma unroll 8
                for (int t = 0; t < 64; t++) acc = fmaf(sr[t], outw[k * 64 + t], acc);
                out[b * 6 + k] = acc;
            }
        }
    }
}

// ---------------- launch ----------------
extern "C" void kernel_launch(void* const* d_in, const int* in_sizes, int n_in,
                              void* d_out, int out_size)
{
    const float* x       = (const float*)d_in[0];
    const float* conv1_w = (const float*)d_in[1];
    const float* conv1_b = (const float*)d_in[2];
    const float* bn1_g   = (const float*)d_in[3];
    const float* bn1_b   = (const float*)d_in[4];
    const float* bn1_m   = (const float*)d_in[5];
    const float* bn1_v   = (const float*)d_in[6];
    const float* conv2_w = (const float*)d_in[7];
    const float* conv2_b = (const float*)d_in[8];
    const float* bn2_g   = (const float*)d_in[9];
    const float* bn2_b   = (const float*)d_in[10];
    const float* bn2_m   = (const float*)d_in[11];
    const float* bn2_v   = (const float*)d_in[12];
    const float* pre_w1  = (const float*)d_in[13];
    const float* pre_b1  = (const float*)d_in[14];
    const float* pre_w2  = (const float*)d_in[15];
    const float* pre_b2  = (const float*)d_in[16];
    const float* pre_w3  = (const float*)d_in[17];
    const float* pre_b3  = (const float*)d_in[18];
    const float* lstm_wih = (const float*)d_in[19];
    const float* lstm_whh = (const float*)d_in[20];
    const float* lstm_bih = (const float*)d_in[21];
    const float* lstm_bhh = (const float*)d_in[22];
    const float* hn0     = (const float*)d_in[23];
    const float* out_w   = (const float*)d_in[24];
    const float* out_b   = (const float*)d_in[25];
    float* out = (float*)d_out;

    dim3 gridA(FRAMES, 12);
    conv1_kernel<<<gridA, 128>>>(x, conv1_w, conv1_b, bn1_g, bn1_b, bn1_m, bn1_v);
    conv2_kernel<<<FRAMES / 8, 256>>>(conv2_w, conv2_b, bn2_g, bn2_b, bn2_m, bn2_v);
    gate_kernel<<<1, 1024>>>(pre_w1, pre_b1, pre_w2, pre_b2, pre_w3, pre_b3);
    lstm_kernel<<<6, 128>>>(lstm_wih, lstm_whh, lstm_bih, lstm_bhh, hn0, out_w, out_b, out);
}